// round 3
// baseline (speedup 1.0000x reference)
#include <cuda_runtime.h>
#include <math.h>

#define NE      50000
#define DIM     64
#define NREL    400
#define NLAYERS 3
#define BS      4
#define NEDGE   400000
#define MAXSLOTS (BS * NE)
#define FULL 0xffffffffu

// ---------------- persistent device scratch (static, no allocation) ----------
__device__ float        g_h[MAXSLOTS * DIM];     // h for active slots
__device__ float        g_agg[MAXSLOTS * DIM];   // message accumulator
__device__ int          g_slotmap[BS * NE];      // slot+1, 0 = free, -1 = claim in progress
__device__ unsigned int g_mask[NE];              // bit b = node active (at layer start)
__device__ int          g_nlist[MAXSLOTS];       // packed (node<<2)|b
__device__ int          g_cnt[4];                // 0: slot alloc, 1: nlist count
__device__ unsigned int g_done;                  // completion counter for init

// ---------------- fused reset + seed (last block seeds) ----------------
__global__ void k_init(const float* __restrict__ ent, const float* __restrict__ qemb,
                       const int* __restrict__ source, const int* __restrict__ qrel) {
    int i = blockIdx.x * blockDim.x + threadIdx.x;
    int stride = gridDim.x * blockDim.x;
    for (int j = i; j < BS * NE; j += stride) g_slotmap[j] = 0;
    for (int j = i; j < NE; j += stride) g_mask[j] = 0u;
    __threadfence();
    __syncthreads();
    __shared__ int amLast;
    if (threadIdx.x == 0) {
        unsigned t = atomicAdd(&g_done, 1u);
        amLast = (t == gridDim.x - 1u);
        if (amLast) g_done = 0u;
    }
    __syncthreads();
    if (!amLast) return;
    // seed (zeroing of slotmap/mask globally visible via threadfence+atomic chain)
    int w = threadIdx.x >> 5, lane = threadIdx.x & 31;
    if (w < BS) {
        int n = source[w];
        int r = qrel[w];
        if (lane == 0) {
            g_slotmap[w * NE + n] = w + 1;          // slot = batch index
            atomicOr(&g_mask[n], 1u << w);
            g_nlist[w] = (n << 2) | w;
        }
        g_h[w * DIM + lane]      = ent[n * DIM + lane]      + qemb[r * DIM + lane];
        g_h[w * DIM + lane + 32] = ent[n * DIM + lane + 32] + qemb[r * DIM + lane + 32];
        g_agg[w * DIM + lane] = 0.f;
        g_agg[w * DIM + lane + 32] = 0.f;
    }
    if (threadIdx.x == 0) { g_cnt[0] = BS; g_cnt[1] = BS; }
}

// ---------------- per-layer fused: scan + activate + message -----------------
// Phase A: each thread tests one edge against the (stable) g_mask snapshot and
// pushes active (edge,batch) pairs into a block-shared queue.
// Phase B: warps drain the queue. Weights are loaded into smem LAZILY — only
// when a block first encounters a non-empty tile.
__global__ void k_edge(const int* __restrict__ esrc, const int* __restrict__ etgt,
                       const int* __restrict__ erel,
                       const float* __restrict__ msgW, const float* __restrict__ gateW,
                       const float* __restrict__ rele, int layer) {
    __shared__ float sM[DIM * DIM];
    __shared__ float sG[DIM * DIM];
    __shared__ int   q[256 * BS];
    __shared__ int   qn;
    __shared__ float sh[8][DIM];
    int lane = threadIdx.x & 31;
    int wl   = threadIdx.x >> 5;
    int loaded = 0;   // uniform across block (branched on shared qn after barrier)

    for (int base = blockIdx.x * 256; base < NEDGE; base += gridDim.x * 256) {
        if (threadIdx.x == 0) qn = 0;
        __syncthreads();
        int e = base + threadIdx.x;
        if (e < NEDGE) {
            unsigned m = g_mask[esrc[e]];
            while (m) {
                int b = __ffs((int)m) - 1;
                m &= m - 1;
                int pos = atomicAdd(&qn, 1);
                q[pos] = (e << 2) | b;
            }
        }
        __syncthreads();
        int total = qn;
        if (total > 0) {
            if (!loaded) {
                for (int i = threadIdx.x; i < DIM * DIM; i += blockDim.x) {
                    sM[i] = msgW[layer * DIM * DIM + i];
                    sG[i] = gateW[layer * DIM * DIM + i];
                }
                loaded = 1;
                __syncthreads();
            }
            for (int idx = wl; idx < total; idx += 8) {
                int p = q[idx];
                int e2 = p >> 2, b = p & 3;
                int s = esrc[e2], t = etgt[e2], r = erel[e2];
                int ss = g_slotmap[b * NE + s] - 1;

                // --- claim / resolve target slot ---
                int* sp = &g_slotmap[b * NE + t];
                int cur;
                if (lane == 0) cur = atomicCAS(sp, 0, -1);
                cur = __shfl_sync(FULL, cur, 0);
                int ts;
                if (cur == 0) {                       // this warp claimed the slot
                    int slot;
                    if (lane == 0) slot = atomicAdd(&g_cnt[0], 1);
                    slot = __shfl_sync(FULL, slot, 0);
                    g_h[slot * DIM + lane] = 0.f;       g_h[slot * DIM + lane + 32] = 0.f;
                    g_agg[slot * DIM + lane] = 0.f;     g_agg[slot * DIM + lane + 32] = 0.f;
                    __syncwarp();
                    __threadfence();
                    if (lane == 0) {
                        int ni = atomicAdd(&g_cnt[1], 1);
                        g_nlist[ni] = (t << 2) | b;
                        atomicExch(sp, slot + 1);       // publish
                    }
                    ts = slot;
                } else if (cur > 0) {
                    ts = cur - 1;
                } else {                               // another warp is initializing: spin
                    if (lane == 0) { do { cur = atomicAdd(sp, 0); } while (cur <= 0); }
                    cur = __shfl_sync(FULL, cur, 0);
                    ts = cur - 1;
                }

                // --- message matvec ---
                sh[wl][lane]      = g_h[ss * DIM + lane];
                sh[wl][lane + 32] = g_h[ss * DIM + lane + 32];
                __syncwarp();
                float m0 = 0.f, m1 = 0.f, q0 = 0.f, q1 = 0.f;
                #pragma unroll 8
                for (int k = 0; k < DIM; k++) {
                    float hk = sh[wl][k];
                    m0 = fmaf(hk, sM[k * DIM + lane],      m0);
                    m1 = fmaf(hk, sM[k * DIM + lane + 32], m1);
                    q0 = fmaf(hk, sG[k * DIM + lane],      q0);
                    q1 = fmaf(hk, sG[k * DIM + lane + 32], q1);
                }
                const float* rr = rele + (size_t)(layer * NREL + r) * DIM;
                float v0 = m0 * rr[lane]      * (1.f / (1.f + expf(-q0)));
                float v1 = m1 * rr[lane + 32] * (1.f / (1.f + expf(-q1)));
                atomicAdd(&g_agg[ts * DIM + lane],      v0);
                atomicAdd(&g_agg[ts * DIM + lane + 32], v1);
                __syncwarp();
            }
        }
        __syncthreads();
    }
}

// ---------------- per-layer: node update + layernorm (warp per active node) --
// Blocks with no work exit BEFORE touching the 32KB weight tile.
__global__ void k_update(const float* __restrict__ updW, const float* __restrict__ updb,
                         const float* __restrict__ lng, const float* __restrict__ lnb,
                         int layer) {
    int total = g_cnt[1];
    if ((int)(blockIdx.x * (blockDim.x >> 5)) >= total) return;   // no work for this block
    __shared__ float sW[2 * DIM * DIM];   // 32 KB
    __shared__ float sx[8][2 * DIM];
    for (int i = threadIdx.x; i < 2 * DIM * DIM; i += blockDim.x)
        sW[i] = updW[layer * 2 * DIM * DIM + i];
    __syncthreads();
    int gw = (blockIdx.x * blockDim.x + threadIdx.x) >> 5;
    int lane = threadIdx.x & 31;
    int wl = threadIdx.x >> 5;
    int nw = (gridDim.x * blockDim.x) >> 5;
    for (int idx = gw; idx < total; idx += nw) {
        int p = g_nlist[idx];
        int n = p >> 2, b = p & 3;
        int slot = g_slotmap[b * NE + n] - 1;
        if (lane == 0) atomicOr(&g_mask[n], 1u << b);   // commit activation
        float h0 = g_h[slot * DIM + lane],   h1 = g_h[slot * DIM + lane + 32];
        float a0 = g_agg[slot * DIM + lane], a1 = g_agg[slot * DIM + lane + 32];
        sx[wl][lane] = h0; sx[wl][lane + 32] = h1;
        sx[wl][64 + lane] = a0; sx[wl][96 + lane] = a1;
        __syncwarp();
        float u0 = updb[layer * DIM + lane], u1 = updb[layer * DIM + lane + 32];
        #pragma unroll 8
        for (int k = 0; k < 2 * DIM; k++) {
            float xk = sx[wl][k];
            u0 = fmaf(xk, sW[k * DIM + lane],      u0);
            u1 = fmaf(xk, sW[k * DIM + lane + 32], u1);
        }
        u0 = fmaxf(u0, 0.f); u1 = fmaxf(u1, 0.f);
        float x0 = h0 + u0, x1 = h1 + u1;
        float s = x0 + x1;
        #pragma unroll
        for (int o = 16; o > 0; o >>= 1) s += __shfl_xor_sync(FULL, s, o);
        float mean = s * (1.f / 64.f);
        float d0 = x0 - mean, d1 = x1 - mean;
        float v = d0 * d0 + d1 * d1;
        #pragma unroll
        for (int o = 16; o > 0; o >>= 1) v += __shfl_xor_sync(FULL, v, o);
        float inv = rsqrtf(v * (1.f / 64.f) + 1e-5f);
        g_h[slot * DIM + lane]      = d0 * inv * lng[layer * DIM + lane]      + lnb[layer * DIM + lane];
        g_h[slot * DIM + lane + 32] = d1 * inv * lng[layer * DIM + lane + 32] + lnb[layer * DIM + lane + 32];
        g_agg[slot * DIM + lane] = 0.f;
        g_agg[slot * DIM + lane + 32] = 0.f;
        __syncwarp();
    }
}

// ---------------- fused scoring ----------------
// Work items: nBg = ceil(NE/4) warp-items (4 background nodes each, skipping
// active (b,n) pairs via g_mask), then nAct active items (full [h,te] score).
__global__ void k_score(const float* __restrict__ ent, const float* __restrict__ sW1,
                        const float* __restrict__ sb1, const float* __restrict__ sW2,
                        const float* __restrict__ sb2, float* __restrict__ out) {
    __shared__ float2 sw[2 * DIM * 32];  // 32 KB: sw[k*32+j] = (W1[k][j], W1[k][j+32])
    __shared__ float sb[DIM];
    __shared__ float sv[DIM];
    __shared__ float te[8][4 * DIM];     // 8 KB staging
    for (int i = threadIdx.x; i < 2 * DIM * 32; i += blockDim.x) {
        int k = i >> 5, j = i & 31;
        sw[i] = make_float2(sW1[k * DIM + j], sW1[k * DIM + j + 32]);
    }
    for (int i = threadIdx.x; i < DIM; i += blockDim.x) { sb[i] = sb1[i]; sv[i] = sW2[i]; }
    __syncthreads();
    float b2 = sb2[0];
    int nAct = g_cnt[1];
    const int nBg = (NE + 3) / 4;
    int W = nBg + nAct;
    int gw = (blockIdx.x * blockDim.x + threadIdx.x) >> 5;
    int lane = threadIdx.x & 31;
    int wl = threadIdx.x >> 5;
    int nw = (gridDim.x * blockDim.x) >> 5;
    for (int w = gw; w < W; w += nw) {
        if (w < nBg) {
            // ---- background: 4 nodes, h = 0 → only rows [64,128) of sW1 ----
            int n0 = w * 4;
            int nvalid = min(4, NE - n0);
            #pragma unroll
            for (int j = 0; j < 4; j++) {
                if (j < nvalid) {
                    te[wl][j * DIM + lane]      = ent[(n0 + j) * DIM + lane];
                    te[wl][j * DIM + lane + 32] = ent[(n0 + j) * DIM + lane + 32];
                }
            }
            __syncwarp();
            float s0[4], s1[4];
            #pragma unroll
            for (int j = 0; j < 4; j++) { s0[j] = sb[lane]; s1[j] = sb[lane + 32]; }
            #pragma unroll 4
            for (int k = 0; k < DIM; k++) {
                float2 wv = sw[(DIM + k) * 32 + lane];
                #pragma unroll
                for (int j = 0; j < 4; j++) {
                    float t = te[wl][j * DIM + k];
                    s0[j] = fmaf(t, wv.x, s0[j]);
                    s1[j] = fmaf(t, wv.y, s1[j]);
                }
            }
            #pragma unroll
            for (int j = 0; j < 4; j++) {
                float a = fmaxf(s0[j], 0.f) * sv[lane] + fmaxf(s1[j], 0.f) * sv[lane + 32];
                #pragma unroll
                for (int o = 16; o > 0; o >>= 1) a += __shfl_xor_sync(FULL, a, o);
                if (lane == 0 && j < nvalid) {
                    int n = n0 + j;
                    float sc = a + b2;
                    unsigned m = g_mask[n];
                    if (!(m & 1u)) out[0 * NE + n] = sc;
                    if (!(m & 2u)) out[1 * NE + n] = sc;
                    if (!(m & 4u)) out[2 * NE + n] = sc;
                    if (!(m & 8u)) out[3 * NE + n] = sc;
                }
            }
            __syncwarp();
        } else {
            // ---- active (b,n): full [h, te] @ sW1 ----
            int p = g_nlist[w - nBg];
            int n = p >> 2, b = p & 3;
            int slot = g_slotmap[b * NE + n] - 1;
            te[wl][lane]      = g_h[slot * DIM + lane];
            te[wl][lane + 32] = g_h[slot * DIM + lane + 32];
            te[wl][64 + lane] = ent[n * DIM + lane];
            te[wl][96 + lane] = ent[n * DIM + lane + 32];
            __syncwarp();
            float s0 = sb[lane], s1 = sb[lane + 32];
            #pragma unroll 8
            for (int k = 0; k < 2 * DIM; k++) {
                float xk = te[wl][k];
                float2 wv = sw[k * 32 + lane];
                s0 = fmaf(xk, wv.x, s0);
                s1 = fmaf(xk, wv.y, s1);
            }
            float a = fmaxf(s0, 0.f) * sv[lane] + fmaxf(s1, 0.f) * sv[lane + 32];
            #pragma unroll
            for (int o = 16; o > 0; o >>= 1) a += __shfl_xor_sync(FULL, a, o);
            if (lane == 0) out[b * NE + n] = a + b2;
            __syncwarp();
        }
    }
}

extern "C" void kernel_launch(void* const* d_in, const int* in_sizes, int n_in,
                              void* d_out, int out_size) {
    const float* ent   = (const float*)d_in[0];
    const float* qemb  = (const float*)d_in[1];
    const float* rele  = (const float*)d_in[2];
    const float* msgW  = (const float*)d_in[3];
    const float* gateW = (const float*)d_in[4];
    const float* updW  = (const float*)d_in[5];
    const float* updb  = (const float*)d_in[6];
    const float* lng   = (const float*)d_in[7];
    const float* lnb   = (const float*)d_in[8];
    const float* sW1   = (const float*)d_in[9];
    const float* sb1   = (const float*)d_in[10];
    const float* sW2   = (const float*)d_in[11];
    const float* sb2   = (const float*)d_in[12];
    const int* source  = (const int*)d_in[13];
    const int* qrel    = (const int*)d_in[14];
    const int* esrc    = (const int*)d_in[15];
    const int* etgt    = (const int*)d_in[16];
    const int* erel    = (const int*)d_in[17];
    float* out = (float*)d_out;

    k_init<<<200, 256>>>(ent, qemb, source, qrel);
    for (int l = 0; l < NLAYERS; l++) {
        k_edge<<<400, 256>>>(esrc, etgt, erel, msgW, gateW, rele, l);
        k_update<<<64, 256>>>(updW, updb, lng, lnb, l);
    }
    k_score<<<296, 256>>>(ent, sW1, sb1, sW2, sb2, out);
}

// round 4
// speedup vs baseline: 1.0169x; 1.0169x over previous
#include <cuda_runtime.h>
#include <math.h>

#define NE      50000
#define DIM     64
#define NREL    400
#define NLAYERS 3
#define BS      4
#define NEDGE   400000
#define MAXSLOTS (BS * NE)
#define FULL 0xffffffffu

// ---------------- persistent device scratch (static, no allocation) ----------
__device__ float        g_h[MAXSLOTS * DIM];     // h for active slots
__device__ float        g_agg[MAXSLOTS * DIM];   // message accumulator
__device__ int          g_slotmap[BS * NE];      // slot+1, 0 = free, -1 = claim in progress
__device__ unsigned int g_mask[NE];              // bit b = node active (at layer start)
__device__ int          g_elist[BS * NEDGE];     // packed (edge<<2)|b, compacted
__device__ int          g_nlist[MAXSLOTS];       // packed (node<<2)|b
__device__ int          g_cnt[8];                // 0: slot alloc, 1: nlist count, 2+l: edges layer l
__device__ unsigned int g_done;                  // completion counter for init

// ---------------- fused reset + seed (last block seeds) ----------------
__global__ void k_init(const float* __restrict__ ent, const float* __restrict__ qemb,
                       const int* __restrict__ source, const int* __restrict__ qrel) {
    int i = blockIdx.x * blockDim.x + threadIdx.x;
    int stride = gridDim.x * blockDim.x;
    int4 z4 = make_int4(0, 0, 0, 0);
    for (int j = i; j < BS * NE / 4; j += stride) ((int4*)g_slotmap)[j] = z4;
    for (int j = i; j < NE / 4; j += stride) ((int4*)g_mask)[j] = z4;
    __threadfence();
    __syncthreads();
    __shared__ int amLast;
    if (threadIdx.x == 0) {
        unsigned t = atomicAdd(&g_done, 1u);
        amLast = (t == gridDim.x - 1u);
        if (amLast) g_done = 0u;
    }
    __syncthreads();
    if (!amLast) return;
    int w = threadIdx.x >> 5, lane = threadIdx.x & 31;
    if (w < BS) {
        int n = source[w];
        int r = qrel[w];
        if (lane == 0) {
            g_slotmap[w * NE + n] = w + 1;          // slot = batch index
            atomicOr(&g_mask[n], 1u << w);
            g_nlist[w] = (n << 2) | w;
        }
        g_h[w * DIM + lane]      = ent[n * DIM + lane]      + qemb[r * DIM + lane];
        g_h[w * DIM + lane + 32] = ent[n * DIM + lane + 32] + qemb[r * DIM + lane + 32];
        g_agg[w * DIM + lane] = 0.f;
        g_agg[w * DIM + lane + 32] = 0.f;
    }
    if (threadIdx.x == 0) {
        g_cnt[0] = BS; g_cnt[1] = BS;
        g_cnt[2] = 0; g_cnt[3] = 0; g_cnt[4] = 0;
    }
}

// ---------------- per-layer streaming scan: compact active (edge,batch) -----
// One int4 (4 edges) per thread, 4 independent mask gathers (MLP=4), warp-
// aggregated append: shfl inclusive scan + one atomicAdd per warp. No smem,
// no block barriers.
__global__ void k_scan(const int* __restrict__ esrc, int layer) {
    int tid = blockIdx.x * blockDim.x + threadIdx.x;
    int lane = threadIdx.x & 31;
    int base = tid * 4;
    int cnt = 0;
    int vals[16];
    if (base < NEDGE) {
        int4 s4 = *reinterpret_cast<const int4*>(esrc + base);
        unsigned m0 = g_mask[s4.x];
        unsigned m1 = g_mask[s4.y];
        unsigned m2 = g_mask[s4.z];
        unsigned m3 = g_mask[s4.w];
        unsigned mm[4] = {m0, m1, m2, m3};
        #pragma unroll
        for (int j = 0; j < 4; j++) {
            unsigned m = mm[j];
            while (m) {
                int b = __ffs((int)m) - 1;
                m &= m - 1;
                vals[cnt++] = ((base + j) << 2) | b;
            }
        }
    }
    // warp-aggregated append (all 32 lanes converged here)
    int x = cnt;
    #pragma unroll
    for (int o = 1; o < 32; o <<= 1) {
        int y = __shfl_up_sync(FULL, x, o);
        if (lane >= o) x += y;
    }
    int warpTotal = __shfl_sync(FULL, x, 31);
    int basePos = 0;
    if (warpTotal > 0) {
        if (lane == 31) basePos = atomicAdd(&g_cnt[2 + layer], warpTotal);
        basePos = __shfl_sync(FULL, basePos, 31);
        int myPos = basePos + x - cnt;
        for (int j = 0; j < cnt; j++) g_elist[myPos + j] = vals[j];
    }
}

// ---------------- per-layer: activate targets + message matvec ---------------
// Warp per compacted edge. Blocks beyond the work exit before the weight load.
__global__ void k_msg(const int* __restrict__ esrc, const int* __restrict__ etgt,
                      const int* __restrict__ erel,
                      const float* __restrict__ msgW, const float* __restrict__ gateW,
                      const float* __restrict__ rele, int layer) {
    int total = g_cnt[2 + layer];
    if ((int)(blockIdx.x * (blockDim.x >> 5)) >= total) return;
    __shared__ float sM[DIM * DIM];
    __shared__ float sG[DIM * DIM];
    __shared__ float sh[8][DIM];
    for (int i = threadIdx.x; i < DIM * DIM; i += blockDim.x) {
        sM[i] = msgW[layer * DIM * DIM + i];
        sG[i] = gateW[layer * DIM * DIM + i];
    }
    __syncthreads();
    int lane = threadIdx.x & 31;
    int wl   = threadIdx.x >> 5;
    int gw = (blockIdx.x * blockDim.x + threadIdx.x) >> 5;
    int nw = (gridDim.x * blockDim.x) >> 5;
    for (int idx = gw; idx < total; idx += nw) {
        int p = g_elist[idx];
        int e = p >> 2, b = p & 3;
        int s = esrc[e], t = etgt[e], r = erel[e];
        int ss = g_slotmap[b * NE + s] - 1;

        // --- claim / resolve target slot ---
        int* sp = &g_slotmap[b * NE + t];
        int cur;
        if (lane == 0) cur = atomicCAS(sp, 0, -1);
        cur = __shfl_sync(FULL, cur, 0);
        int ts;
        if (cur == 0) {                       // this warp claimed the slot
            int slot;
            if (lane == 0) slot = atomicAdd(&g_cnt[0], 1);
            slot = __shfl_sync(FULL, slot, 0);
            g_h[slot * DIM + lane] = 0.f;       g_h[slot * DIM + lane + 32] = 0.f;
            g_agg[slot * DIM + lane] = 0.f;     g_agg[slot * DIM + lane + 32] = 0.f;
            __syncwarp();
            __threadfence();
            if (lane == 0) {
                int ni = atomicAdd(&g_cnt[1], 1);
                g_nlist[ni] = (t << 2) | b;
                atomicExch(sp, slot + 1);       // publish
            }
            ts = slot;
        } else if (cur > 0) {
            ts = cur - 1;
        } else {                               // another warp is initializing: spin
            if (lane == 0) { do { cur = atomicAdd(sp, 0); } while (cur <= 0); }
            cur = __shfl_sync(FULL, cur, 0);
            ts = cur - 1;
        }

        // --- message matvec ---
        sh[wl][lane]      = g_h[ss * DIM + lane];
        sh[wl][lane + 32] = g_h[ss * DIM + lane + 32];
        __syncwarp();
        float m0 = 0.f, m1 = 0.f, q0 = 0.f, q1 = 0.f;
        #pragma unroll 8
        for (int k = 0; k < DIM; k++) {
            float hk = sh[wl][k];
            m0 = fmaf(hk, sM[k * DIM + lane],      m0);
            m1 = fmaf(hk, sM[k * DIM + lane + 32], m1);
            q0 = fmaf(hk, sG[k * DIM + lane],      q0);
            q1 = fmaf(hk, sG[k * DIM + lane + 32], q1);
        }
        const float* rr = rele + (size_t)(layer * NREL + r) * DIM;
        float v0 = m0 * rr[lane]      * (1.f / (1.f + expf(-q0)));
        float v1 = m1 * rr[lane + 32] * (1.f / (1.f + expf(-q1)));
        atomicAdd(&g_agg[ts * DIM + lane],      v0);
        atomicAdd(&g_agg[ts * DIM + lane + 32], v1);
        __syncwarp();
    }
}

// ---------------- per-layer: node update + layernorm (warp per active node) --
__global__ void k_update(const float* __restrict__ updW, const float* __restrict__ updb,
                         const float* __restrict__ lng, const float* __restrict__ lnb,
                         int layer) {
    int total = g_cnt[1];
    if ((int)(blockIdx.x * (blockDim.x >> 5)) >= total) return;
    __shared__ float sW[2 * DIM * DIM];   // 32 KB
    __shared__ float sx[8][2 * DIM];
    for (int i = threadIdx.x; i < 2 * DIM * DIM; i += blockDim.x)
        sW[i] = updW[layer * 2 * DIM * DIM + i];
    __syncthreads();
    int gw = (blockIdx.x * blockDim.x + threadIdx.x) >> 5;
    int lane = threadIdx.x & 31;
    int wl = threadIdx.x >> 5;
    int nw = (gridDim.x * blockDim.x) >> 5;
    for (int idx = gw; idx < total; idx += nw) {
        int p = g_nlist[idx];
        int n = p >> 2, b = p & 3;
        int slot = g_slotmap[b * NE + n] - 1;
        if (lane == 0) atomicOr(&g_mask[n], 1u << b);   // commit activation
        float h0 = g_h[slot * DIM + lane],   h1 = g_h[slot * DIM + lane + 32];
        float a0 = g_agg[slot * DIM + lane], a1 = g_agg[slot * DIM + lane + 32];
        sx[wl][lane] = h0; sx[wl][lane + 32] = h1;
        sx[wl][64 + lane] = a0; sx[wl][96 + lane] = a1;
        __syncwarp();
        float u0 = updb[layer * DIM + lane], u1 = updb[layer * DIM + lane + 32];
        #pragma unroll 8
        for (int k = 0; k < 2 * DIM; k++) {
            float xk = sx[wl][k];
            u0 = fmaf(xk, sW[k * DIM + lane],      u0);
            u1 = fmaf(xk, sW[k * DIM + lane + 32], u1);
        }
        u0 = fmaxf(u0, 0.f); u1 = fmaxf(u1, 0.f);
        float x0 = h0 + u0, x1 = h1 + u1;
        float s = x0 + x1;
        #pragma unroll
        for (int o = 16; o > 0; o >>= 1) s += __shfl_xor_sync(FULL, s, o);
        float mean = s * (1.f / 64.f);
        float d0 = x0 - mean, d1 = x1 - mean;
        float v = d0 * d0 + d1 * d1;
        #pragma unroll
        for (int o = 16; o > 0; o >>= 1) v += __shfl_xor_sync(FULL, v, o);
        float inv = rsqrtf(v * (1.f / 64.f) + 1e-5f);
        g_h[slot * DIM + lane]      = d0 * inv * lng[layer * DIM + lane]      + lnb[layer * DIM + lane];
        g_h[slot * DIM + lane + 32] = d1 * inv * lng[layer * DIM + lane + 32] + lnb[layer * DIM + lane + 32];
        g_agg[slot * DIM + lane] = 0.f;
        g_agg[slot * DIM + lane + 32] = 0.f;
        __syncwarp();
    }
}

// ---------------- fused scoring ----------------
__global__ void k_score(const float* __restrict__ ent, const float* __restrict__ sW1,
                        const float* __restrict__ sb1, const float* __restrict__ sW2,
                        const float* __restrict__ sb2, float* __restrict__ out) {
    __shared__ float2 sw[2 * DIM * 32];  // 32 KB: sw[k*32+j] = (W1[k][j], W1[k][j+32])
    __shared__ float sb[DIM];
    __shared__ float sv[DIM];
    __shared__ float te[8][4 * DIM];     // 8 KB staging
    for (int i = threadIdx.x; i < 2 * DIM * 32; i += blockDim.x) {
        int k = i >> 5, j = i & 31;
        sw[i] = make_float2(sW1[k * DIM + j], sW1[k * DIM + j + 32]);
    }
    for (int i = threadIdx.x; i < DIM; i += blockDim.x) { sb[i] = sb1[i]; sv[i] = sW2[i]; }
    __syncthreads();
    float b2 = sb2[0];
    int nAct = g_cnt[1];
    const int nBg = (NE + 3) / 4;
    int W = nBg + nAct;
    int gw = (blockIdx.x * blockDim.x + threadIdx.x) >> 5;
    int lane = threadIdx.x & 31;
    int wl = threadIdx.x >> 5;
    int nw = (gridDim.x * blockDim.x) >> 5;
    for (int w = gw; w < W; w += nw) {
        if (w < nBg) {
            // ---- background: 4 nodes, h = 0 → only rows [64,128) of sW1 ----
            int n0 = w * 4;
            int nvalid = min(4, NE - n0);
            #pragma unroll
            for (int j = 0; j < 4; j++) {
                if (j < nvalid) {
                    te[wl][j * DIM + lane]      = ent[(n0 + j) * DIM + lane];
                    te[wl][j * DIM + lane + 32] = ent[(n0 + j) * DIM + lane + 32];
                }
            }
            __syncwarp();
            float s0[4], s1[4];
            #pragma unroll
            for (int j = 0; j < 4; j++) { s0[j] = sb[lane]; s1[j] = sb[lane + 32]; }
            #pragma unroll 4
            for (int k = 0; k < DIM; k++) {
                float2 wv = sw[(DIM + k) * 32 + lane];
                #pragma unroll
                for (int j = 0; j < 4; j++) {
                    float t = te[wl][j * DIM + k];
                    s0[j] = fmaf(t, wv.x, s0[j]);
                    s1[j] = fmaf(t, wv.y, s1[j]);
                }
            }
            #pragma unroll
            for (int j = 0; j < 4; j++) {
                float a = fmaxf(s0[j], 0.f) * sv[lane] + fmaxf(s1[j], 0.f) * sv[lane + 32];
                #pragma unroll
                for (int o = 16; o > 0; o >>= 1) a += __shfl_xor_sync(FULL, a, o);
                if (lane == 0 && j < nvalid) {
                    int n = n0 + j;
                    float sc = a + b2;
                    unsigned m = g_mask[n];
                    if (!(m & 1u)) out[0 * NE + n] = sc;
                    if (!(m & 2u)) out[1 * NE + n] = sc;
                    if (!(m & 4u)) out[2 * NE + n] = sc;
                    if (!(m & 8u)) out[3 * NE + n] = sc;
                }
            }
            __syncwarp();
        } else {
            // ---- active (b,n): full [h, te] @ sW1 ----
            int p = g_nlist[w - nBg];
            int n = p >> 2, b = p & 3;
            int slot = g_slotmap[b * NE + n] - 1;
            te[wl][lane]      = g_h[slot * DIM + lane];
            te[wl][lane + 32] = g_h[slot * DIM + lane + 32];
            te[wl][64 + lane] = ent[n * DIM + lane];
            te[wl][96 + lane] = ent[n * DIM + lane + 32];
            __syncwarp();
            float s0 = sb[lane], s1 = sb[lane + 32];
            #pragma unroll 8
            for (int k = 0; k < 2 * DIM; k++) {
                float xk = te[wl][k];
                float2 wv = sw[k * 32 + lane];
                s0 = fmaf(xk, wv.x, s0);
                s1 = fmaf(xk, wv.y, s1);
            }
            float a = fmaxf(s0, 0.f) * sv[lane] + fmaxf(s1, 0.f) * sv[lane + 32];
            #pragma unroll
            for (int o = 16; o > 0; o >>= 1) a += __shfl_xor_sync(FULL, a, o);
            if (lane == 0) out[b * NE + n] = a + b2;
            __syncwarp();
        }
    }
}

extern "C" void kernel_launch(void* const* d_in, const int* in_sizes, int n_in,
                              void* d_out, int out_size) {
    const float* ent   = (const float*)d_in[0];
    const float* qemb  = (const float*)d_in[1];
    const float* rele  = (const float*)d_in[2];
    const float* msgW  = (const float*)d_in[3];
    const float* gateW = (const float*)d_in[4];
    const float* updW  = (const float*)d_in[5];
    const float* updb  = (const float*)d_in[6];
    const float* lng   = (const float*)d_in[7];
    const float* lnb   = (const float*)d_in[8];
    const float* sW1   = (const float*)d_in[9];
    const float* sb1   = (const float*)d_in[10];
    const float* sW2   = (const float*)d_in[11];
    const float* sb2   = (const float*)d_in[12];
    const int* source  = (const int*)d_in[13];
    const int* qrel    = (const int*)d_in[14];
    const int* esrc    = (const int*)d_in[15];
    const int* etgt    = (const int*)d_in[16];
    const int* erel    = (const int*)d_in[17];
    float* out = (float*)d_out;

    k_init<<<200, 256>>>(ent, qemb, source, qrel);
    for (int l = 0; l < NLAYERS; l++) {
        k_scan<<<(NEDGE / 4 + 255) / 256, 256>>>(esrc, l);
        k_msg<<<64, 256>>>(esrc, etgt, erel, msgW, gateW, rele, l);
        k_update<<<64, 256>>>(updW, updb, lng, lnb, l);
    }
    k_score<<<296, 256>>>(ent, sW1, sb1, sW2, sb2, out);
}

// round 5
// speedup vs baseline: 1.3952x; 1.3720x over previous
#include <cuda_runtime.h>
#include <math.h>

#define NE      50000
#define DIM     64
#define NREL    400
#define NLAYERS 3
#define BS      4
#define NEDGE   400000
#define MAXSLOTS (BS * NE)
#define FULL 0xffffffffu
#define TPB 256

// ---------------- persistent device scratch (static, no allocation) ----------
__device__ float        g_h[MAXSLOTS * DIM];
__device__ float        g_agg[MAXSLOTS * DIM];
__device__ int          g_slotmap[BS * NE];      // slot+1, 0 = free, -1 = claiming
__device__ unsigned int g_mask[NE];              // bit b = (b,node) active
__device__ int          g_elist[BS * NEDGE];     // packed (edge<<2)|b
__device__ int          g_nlist[MAXSLOTS];       // packed (node<<2)|b
__device__ int          g_cnt[8];                // 0 slots, 1 nlist, 2+l edges/layer
__device__ unsigned int g_bar[16];               // device barrier counters (zeroed at exit)

struct SMemMsg { float M[DIM * DIM]; float G[DIM * DIM]; float sh[8][DIM]; };
struct SMemUpd { float W[2 * DIM * DIM]; float x[8][2 * DIM]; };
struct SMemSc  { float2 w[2 * DIM * 32]; float te[8][4 * DIM]; };
union SMemAll { SMemMsg m; SMemUpd u; SMemSc s; };

// Grid-wide barrier: all blocks resident by construction (grid = SMs * occupancy).
__device__ __forceinline__ void gbar(int i) {
    __syncthreads();
    if (threadIdx.x == 0) {
        __threadfence();
        atomicAdd(&g_bar[i], 1u);
        while (*(volatile unsigned int*)&g_bar[i] < gridDim.x) __nanosleep(64);
    }
    __syncthreads();
}

// Warp-aggregated append of active (edge,batch) pairs into g_elist.
// All 32 lanes must be converged.
__device__ __forceinline__ void push4(int base, const unsigned mm[4], int cslot, int lane) {
    int cnt = __popc(mm[0]) + __popc(mm[1]) + __popc(mm[2]) + __popc(mm[3]);
    int x = cnt;
    #pragma unroll
    for (int o = 1; o < 32; o <<= 1) {
        int y = __shfl_up_sync(FULL, x, o);
        if (lane >= o) x += y;
    }
    int warpTotal = __shfl_sync(FULL, x, 31);
    if (warpTotal == 0) return;
    int basePos = 0;
    if (lane == 31) basePos = atomicAdd(&g_cnt[cslot], warpTotal);
    basePos = __shfl_sync(FULL, basePos, 31);
    int pos = basePos + x - cnt;
    #pragma unroll
    for (int j = 0; j < 4; j++) {
        unsigned m = mm[j];
        while (m) {
            int b = __ffs((int)m) - 1;
            m &= m - 1;
            g_elist[pos++] = ((base + j) << 2) | b;
        }
    }
}

// Scan all edges against the current mask (L2 reads; mask is stable this phase).
__device__ __forceinline__ void scan_layer(const int* __restrict__ esrc, int layer,
                                           int gwarp, int gwarps, int lane) {
    const int CW = NEDGE / 4 / 32;   // 3125 exactly
    for (int cw = gwarp; cw < CW; cw += gwarps) {
        int c = cw * 32 + lane;
        int base = c * 4;
        int4 e4 = *reinterpret_cast<const int4*>(esrc + base);
        unsigned mm[4];
        mm[0] = __ldcg(&g_mask[e4.x]);
        mm[1] = __ldcg(&g_mask[e4.y]);
        mm[2] = __ldcg(&g_mask[e4.z]);
        mm[3] = __ldcg(&g_mask[e4.w]);
        push4(base, mm, 2 + layer, lane);
    }
}

__global__ void __launch_bounds__(TPB, 2)
k_all(const float* __restrict__ ent, const float* __restrict__ qemb,
      const float* __restrict__ rele, const float* __restrict__ msgW,
      const float* __restrict__ gateW, const float* __restrict__ updW,
      const float* __restrict__ updb, const float* __restrict__ lng,
      const float* __restrict__ lnb, const float* __restrict__ sW1,
      const float* __restrict__ sb1, const float* __restrict__ sW2,
      const float* __restrict__ sb2, const int* __restrict__ source,
      const int* __restrict__ qrel, const int* __restrict__ esrc,
      const int* __restrict__ etgt, const int* __restrict__ erel,
      float* __restrict__ out) {
    __shared__ SMemAll sm;
    const int tid  = threadIdx.x;
    const int lane = tid & 31;
    const int wl   = tid >> 5;
    const int bid  = blockIdx.x;
    const int nb   = gridDim.x;
    const int gthreads = nb * TPB;
    const int gwarps   = gthreads >> 5;
    const int gwarp    = bid * (TPB >> 5) + wl;
    const int gt       = bid * TPB + tid;

    // ---------------- P0: zero slotmap + mask ----------------
    {
        int4 z = make_int4(0, 0, 0, 0);
        for (int j = gt; j < BS * NE / 4; j += gthreads) ((int4*)g_slotmap)[j] = z;
        for (int j = gt; j < NE / 4; j += gthreads) ((int4*)g_mask)[j] = z;
    }
    gbar(0);

    // ---------------- P1: scan layer-0 (vs source ids) + seed ----------------
    {
        int s0 = __ldg(&source[0]), s1 = __ldg(&source[1]);
        int s2 = __ldg(&source[2]), s3 = __ldg(&source[3]);
        const int CW = NEDGE / 4 / 32;
        for (int cw = gwarp; cw < CW; cw += gwarps) {
            int c = cw * 32 + lane;
            int base = c * 4;
            int4 e4 = *reinterpret_cast<const int4*>(esrc + base);
            unsigned mm[4];
            mm[0] = (unsigned)(e4.x == s0) | ((unsigned)(e4.x == s1) << 1) |
                    ((unsigned)(e4.x == s2) << 2) | ((unsigned)(e4.x == s3) << 3);
            mm[1] = (unsigned)(e4.y == s0) | ((unsigned)(e4.y == s1) << 1) |
                    ((unsigned)(e4.y == s2) << 2) | ((unsigned)(e4.y == s3) << 3);
            mm[2] = (unsigned)(e4.z == s0) | ((unsigned)(e4.z == s1) << 1) |
                    ((unsigned)(e4.z == s2) << 2) | ((unsigned)(e4.z == s3) << 3);
            mm[3] = (unsigned)(e4.w == s0) | ((unsigned)(e4.w == s1) << 1) |
                    ((unsigned)(e4.w == s2) << 2) | ((unsigned)(e4.w == s3) << 3);
            push4(base, mm, 2, lane);
        }
        if (bid == 0) {
            if (wl < BS) {
                int n = __ldg(&source[wl]);
                int r = __ldg(&qrel[wl]);
                if (lane == 0) {
                    g_slotmap[wl * NE + n] = wl + 1;
                    atomicOr(&g_mask[n], 1u << wl);
                    g_nlist[wl] = (n << 2) | wl;
                }
                g_h[wl * DIM + lane]      = __ldg(&ent[n * DIM + lane])      + __ldg(&qemb[r * DIM + lane]);
                g_h[wl * DIM + lane + 32] = __ldg(&ent[n * DIM + lane + 32]) + __ldg(&qemb[r * DIM + lane + 32]);
                g_agg[wl * DIM + lane] = 0.f;
                g_agg[wl * DIM + lane + 32] = 0.f;
            }
            if (tid == 0) { g_cnt[0] = BS; g_cnt[1] = BS; }
        }
    }
    gbar(1);

    // ---------------- per-layer: msg, then (update + scan next) ----------------
    for (int l = 0; l < NLAYERS; l++) {
        // ---- msg(l): claim target slots + matvec + atomic scatter ----
        {
            int total = __ldcg(&g_cnt[2 + l]);
            int pb = min(nb, (total + 7) >> 3);
            if (bid < pb) {
                for (int i = tid; i < DIM * DIM; i += TPB) {
                    sm.m.M[i] = __ldg(&msgW[l * DIM * DIM + i]);
                    sm.m.G[i] = __ldg(&gateW[l * DIM * DIM + i]);
                }
                __syncthreads();
                for (int idx = bid * 8 + wl; idx < total; idx += pb * 8) {
                    int p = __ldcg(&g_elist[idx]);
                    int e = p >> 2, b = p & 3;
                    int s = __ldg(&esrc[e]), t = __ldg(&etgt[e]), r = __ldg(&erel[e]);
                    int ss = __ldcg(&g_slotmap[b * NE + s]) - 1;

                    int* sp = &g_slotmap[b * NE + t];
                    int cur;
                    if (lane == 0) cur = atomicCAS(sp, 0, -1);
                    cur = __shfl_sync(FULL, cur, 0);
                    int ts;
                    if (cur == 0) {                       // claimed: init slot
                        int slot;
                        if (lane == 0) slot = atomicAdd(&g_cnt[0], 1);
                        slot = __shfl_sync(FULL, slot, 0);
                        g_h[slot * DIM + lane] = 0.f;       g_h[slot * DIM + lane + 32] = 0.f;
                        g_agg[slot * DIM + lane] = 0.f;     g_agg[slot * DIM + lane + 32] = 0.f;
                        __syncwarp();
                        __threadfence();
                        if (lane == 0) {
                            int ni = atomicAdd(&g_cnt[1], 1);
                            g_nlist[ni] = (t << 2) | b;
                            atomicOr(&g_mask[t], 1u << b);  // commit activation for next scan
                            atomicExch(sp, slot + 1);       // publish
                        }
                        ts = slot;
                    } else if (cur > 0) {
                        ts = cur - 1;
                    } else {                               // spin until published
                        if (lane == 0) { do { cur = atomicAdd(sp, 0); } while (cur <= 0); }
                        cur = __shfl_sync(FULL, cur, 0);
                        ts = cur - 1;
                    }

                    sm.m.sh[wl][lane]      = __ldcg(&g_h[ss * DIM + lane]);
                    sm.m.sh[wl][lane + 32] = __ldcg(&g_h[ss * DIM + lane + 32]);
                    __syncwarp();
                    float m0 = 0.f, m1 = 0.f, q0 = 0.f, q1 = 0.f;
                    #pragma unroll 8
                    for (int k = 0; k < DIM; k++) {
                        float hk = sm.m.sh[wl][k];
                        m0 = fmaf(hk, sm.m.M[k * DIM + lane],      m0);
                        m1 = fmaf(hk, sm.m.M[k * DIM + lane + 32], m1);
                        q0 = fmaf(hk, sm.m.G[k * DIM + lane],      q0);
                        q1 = fmaf(hk, sm.m.G[k * DIM + lane + 32], q1);
                    }
                    const float* rr = rele + (size_t)(l * NREL + r) * DIM;
                    float v0 = __ldg(&rr[lane])      * m0 * (1.f / (1.f + expf(-q0)));
                    float v1 = __ldg(&rr[lane + 32]) * m1 * (1.f / (1.f + expf(-q1)));
                    atomicAdd(&g_agg[ts * DIM + lane],      v0);
                    atomicAdd(&g_agg[ts * DIM + lane + 32], v1);
                    __syncwarp();
                }
            }
        }
        gbar(2 + 2 * l);

        // ---- scan(l+1) (independent of update) ----
        if (l + 1 < NLAYERS) scan_layer(esrc, l + 1, gwarp, gwarps, lane);

        // ---- update(l): h = LN(h + relu([h,agg]@W + b)) over nlist ----
        {
            int total = __ldcg(&g_cnt[1]);
            int pb = min(nb, (total + 7) >> 3);
            if (bid < pb) {
                for (int i = tid; i < 2 * DIM * DIM; i += TPB)
                    sm.u.W[i] = __ldg(&updW[l * 2 * DIM * DIM + i]);
                __syncthreads();
                float ub0 = __ldg(&updb[l * DIM + lane]), ub1 = __ldg(&updb[l * DIM + lane + 32]);
                float lg0 = __ldg(&lng[l * DIM + lane]),  lg1 = __ldg(&lng[l * DIM + lane + 32]);
                float lb0 = __ldg(&lnb[l * DIM + lane]),  lb1 = __ldg(&lnb[l * DIM + lane + 32]);
                for (int idx = bid * 8 + wl; idx < total; idx += pb * 8) {
                    int p = __ldcg(&g_nlist[idx]);
                    int n = p >> 2, b = p & 3;
                    int slot = __ldcg(&g_slotmap[b * NE + n]) - 1;
                    float h0 = __ldcg(&g_h[slot * DIM + lane]);
                    float h1 = __ldcg(&g_h[slot * DIM + lane + 32]);
                    float a0 = __ldcg(&g_agg[slot * DIM + lane]);
                    float a1 = __ldcg(&g_agg[slot * DIM + lane + 32]);
                    sm.u.x[wl][lane] = h0;      sm.u.x[wl][lane + 32] = h1;
                    sm.u.x[wl][64 + lane] = a0; sm.u.x[wl][96 + lane] = a1;
                    __syncwarp();
                    float u0 = ub0, u1 = ub1;
                    #pragma unroll 8
                    for (int k = 0; k < 2 * DIM; k++) {
                        float xk = sm.u.x[wl][k];
                        u0 = fmaf(xk, sm.u.W[k * DIM + lane],      u0);
                        u1 = fmaf(xk, sm.u.W[k * DIM + lane + 32], u1);
                    }
                    u0 = fmaxf(u0, 0.f); u1 = fmaxf(u1, 0.f);
                    float x0 = h0 + u0, x1 = h1 + u1;
                    float sums = x0 + x1;
                    #pragma unroll
                    for (int o = 16; o > 0; o >>= 1) sums += __shfl_xor_sync(FULL, sums, o);
                    float mean = sums * (1.f / 64.f);
                    float d0 = x0 - mean, d1 = x1 - mean;
                    float v = d0 * d0 + d1 * d1;
                    #pragma unroll
                    for (int o = 16; o > 0; o >>= 1) v += __shfl_xor_sync(FULL, v, o);
                    float inv = rsqrtf(v * (1.f / 64.f) + 1e-5f);
                    g_h[slot * DIM + lane]      = d0 * inv * lg0 + lb0;
                    g_h[slot * DIM + lane + 32] = d1 * inv * lg1 + lb1;
                    g_agg[slot * DIM + lane] = 0.f;
                    g_agg[slot * DIM + lane + 32] = 0.f;
                    __syncwarp();
                }
            }
        }
        gbar(3 + 2 * l);
    }

    // ---------------- score ----------------
    {
        for (int i = tid; i < 2 * DIM * 32; i += TPB) {
            int k = i >> 5, j = i & 31;
            sm.s.w[i] = make_float2(__ldg(&sW1[k * DIM + j]), __ldg(&sW1[k * DIM + j + 32]));
        }
        __syncthreads();
        float rb0 = __ldg(&sb1[lane]), rb1 = __ldg(&sb1[lane + 32]);
        float rv0 = __ldg(&sW2[lane]), rv1 = __ldg(&sW2[lane + 32]);
        float b2 = __ldg(&sb2[0]);
        int nAct = __ldcg(&g_cnt[1]);
        const int nBg = NE / 4;       // 12500 exact
        int W = nBg + nAct;
        for (int w = gwarp; w < W; w += gwarps) {
            if (w < nBg) {
                int n0 = w * 4;
                #pragma unroll
                for (int j = 0; j < 4; j++) {
                    sm.s.te[wl][j * DIM + lane]      = __ldg(&ent[(n0 + j) * DIM + lane]);
                    sm.s.te[wl][j * DIM + lane + 32] = __ldg(&ent[(n0 + j) * DIM + lane + 32]);
                }
                __syncwarp();
                float s0[4], s1[4];
                #pragma unroll
                for (int j = 0; j < 4; j++) { s0[j] = rb0; s1[j] = rb1; }
                #pragma unroll 4
                for (int k = 0; k < DIM; k++) {
                    float2 wv = sm.s.w[(DIM + k) * 32 + lane];
                    #pragma unroll
                    for (int j = 0; j < 4; j++) {
                        float t = sm.s.te[wl][j * DIM + k];
                        s0[j] = fmaf(t, wv.x, s0[j]);
                        s1[j] = fmaf(t, wv.y, s1[j]);
                    }
                }
                #pragma unroll
                for (int j = 0; j < 4; j++) {
                    float a = fmaxf(s0[j], 0.f) * rv0 + fmaxf(s1[j], 0.f) * rv1;
                    #pragma unroll
                    for (int o = 16; o > 0; o >>= 1) a += __shfl_xor_sync(FULL, a, o);
                    if (lane == 0) {
                        int n = n0 + j;
                        float sc = a + b2;
                        unsigned m = __ldcg(&g_mask[n]);
                        if (!(m & 1u)) out[0 * NE + n] = sc;
                        if (!(m & 2u)) out[1 * NE + n] = sc;
                        if (!(m & 4u)) out[2 * NE + n] = sc;
                        if (!(m & 8u)) out[3 * NE + n] = sc;
                    }
                }
                __syncwarp();
            } else {
                int p = __ldcg(&g_nlist[w - nBg]);
                int n = p >> 2, b = p & 3;
                int slot = __ldcg(&g_slotmap[b * NE + n]) - 1;
                sm.s.te[wl][lane]      = __ldcg(&g_h[slot * DIM + lane]);
                sm.s.te[wl][lane + 32] = __ldcg(&g_h[slot * DIM + lane + 32]);
                sm.s.te[wl][64 + lane] = __ldg(&ent[n * DIM + lane]);
                sm.s.te[wl][96 + lane] = __ldg(&ent[n * DIM + lane + 32]);
                __syncwarp();
                float s0 = rb0, s1 = rb1;
                #pragma unroll 8
                for (int k = 0; k < 2 * DIM; k++) {
                    float xk = sm.s.te[wl][k];
                    float2 wv = sm.s.w[k * 32 + lane];
                    s0 = fmaf(xk, wv.x, s0);
                    s1 = fmaf(xk, wv.y, s1);
                }
                float a = fmaxf(s0, 0.f) * rv0 + fmaxf(s1, 0.f) * rv1;
                #pragma unroll
                for (int o = 16; o > 0; o >>= 1) a += __shfl_xor_sync(FULL, a, o);
                if (lane == 0) out[b * NE + n] = a + b2;
                __syncwarp();
            }
        }
    }

    // ---------------- final arrive-only barrier + state reset ----------------
    __syncthreads();
    if (tid == 0) {
        __threadfence();
        atomicAdd(&g_bar[15], 1u);
        if (bid == 0) {
            while (*(volatile unsigned int*)&g_bar[15] < (unsigned)nb) __nanosleep(64);
            #pragma unroll
            for (int i = 0; i < 16; i++) g_bar[i] = 0u;
            #pragma unroll
            for (int i = 0; i < 8; i++) g_cnt[i] = 0;
        }
    }
}

extern "C" void kernel_launch(void* const* d_in, const int* in_sizes, int n_in,
                              void* d_out, int out_size) {
    const float* ent   = (const float*)d_in[0];
    const float* qemb  = (const float*)d_in[1];
    const float* rele  = (const float*)d_in[2];
    const float* msgW  = (const float*)d_in[3];
    const float* gateW = (const float*)d_in[4];
    const float* updW  = (const float*)d_in[5];
    const float* updb  = (const float*)d_in[6];
    const float* lng   = (const float*)d_in[7];
    const float* lnb   = (const float*)d_in[8];
    const float* sW1   = (const float*)d_in[9];
    const float* sb1   = (const float*)d_in[10];
    const float* sW2   = (const float*)d_in[11];
    const float* sb2   = (const float*)d_in[12];
    const int* source  = (const int*)d_in[13];
    const int* qrel    = (const int*)d_in[14];
    const int* esrc    = (const int*)d_in[15];
    const int* etgt    = (const int*)d_in[16];
    const int* erel    = (const int*)d_in[17];
    float* out = (float*)d_out;

    // Fully-resident grid (guarantees the device-wide barrier cannot deadlock).
    int dev = 0;
    cudaGetDevice(&dev);
    int sms = 0;
    cudaDeviceGetAttribute(&sms, cudaDevAttrMultiProcessorCount, dev);
    int maxb = 0;
    cudaOccupancyMaxActiveBlocksPerMultiprocessor(&maxb, k_all, TPB, 0);
    if (maxb < 1) maxb = 1;
    int grid = sms * maxb;

    k_all<<<grid, TPB>>>(ent, qemb, rele, msgW, gateW, updW, updb, lng, lnb,
                         sW1, sb1, sW2, sb2, source, qrel, esrc, etgt, erel, out);
}